// round 13
// baseline (speedup 1.0000x reference)
#include <cuda_runtime.h>

// IoU distance: out[i][j] = inter/union + 1e-16
//   inter = min(lw_i, rw_j) * min(lh_i, rh_j)
//   union = lw_i*lh_i + rw_j*rh_j - inter
//
// lhs: [N,2] fp32 (N = 100000), rhs: [512,2] fp32, out: [N,512] fp32.
//
// R13 probe: 256-thread blocks, 2 rows per iteration per block.
// Thread (tr = t>>7, tc = t&127) owns row base+tr, columns 4tc..4tc+3.
// Same per-thread work and pipelined prefetch as the 33.0us champion; half
// the CTA count (3125), lower per-thread register state (1 pipelined row).
// Kept (validated over R2-R12): register-resident rhs, rcp.approx +
// FFMA(+EPS), __stcs evict-first STG.128, chunk=32 -> exact division.

#ifndef EPS_IOU
#define EPS_IOU 1e-16f
#endif

__device__ __forceinline__ float rcp_approx(float x) {
    float r;
    asm("rcp.approx.ftz.f32 %0, %1;" : "=f"(r) : "f"(x));
    return r;
}

__global__ __launch_bounds__(256, 5)
void iou_distance_kernel(const float2* __restrict__ lhs,
                         const float4* __restrict__ rhs4,
                         float4* __restrict__ out4,
                         int chunk,              // rows per block (multiple of 2)
                         int n_rows)
{
    const int t  = threadIdx.x;
    const int tr = t >> 7;        // 0..1 : row lane within the 2-row slab
    const int tc = t & 127;       // 0..127: column quad -> columns 4tc..4tc+3

    // This thread's 4 rhs boxes, register-resident for the whole kernel.
    float rw[4], rh[4], ra[4];
    {
        float4 p0 = rhs4[2 * tc + 0];
        float4 p1 = rhs4[2 * tc + 1];
        rw[0] = p0.x; rh[0] = p0.y;
        rw[1] = p0.z; rh[1] = p0.w;
        rw[2] = p1.x; rh[2] = p1.y;
        rw[3] = p1.z; rh[3] = p1.w;
#pragma unroll
        for (int k = 0; k < 4; ++k) ra[k] = rw[k] * rh[k];
    }

    int row0 = blockIdx.x * chunk;
    if (row0 >= n_rows) return;
    int row_end = row0 + chunk;
    if (row_end > n_rows) row_end = n_rows;
    const int n_it = (row_end - row0) >> 1;      // 2 rows per iteration

    const float2* lp = lhs + row0 + tr;          // this lane's row stream (stride 2)
    float4*       op = out4 + (long long)(row0 + tr) * 128 + tc;

    // Prologue: prefetch this lane's first row.
    float2 lcur = lp[0];
    lp += 2;

    for (int it = 0; it < n_it; ++it) {
        // Prefetch next iteration's row before computing on lcur.
        float2 lnext;
        if (it + 1 < n_it) { lnext = lp[0]; lp += 2; }

        const float lw = lcur.x, lh = lcur.y;
        const float la = lw * lh;

        float o[4];
#pragma unroll
        for (int k = 0; k < 4; ++k) {
            const float iw    = fminf(lw, rw[k]);
            const float ih    = fminf(lh, rh[k]);
            const float inter = iw * ih;                  // FMUL
            const float uni   = (la + ra[k]) - inter;     // FADD, FADD
            o[k] = fmaf(inter, rcp_approx(uni), EPS_IOU); // MUFU + FFMA
        }

        float4 v;
        v.x = o[0]; v.y = o[1]; v.z = o[2]; v.w = o[3];
        __stcs(op, v);                        // evict-first streaming STG.128
        op += 2 * 128;

        lcur = lnext;
    }
}

extern "C" void kernel_launch(void* const* d_in, const int* in_sizes, int n_in,
                              void* d_out, int out_size)
{
    const float2* lhs  = (const float2*)d_in[0];
    const float4* rhs4 = (const float4*)d_in[1];
    float4*       out4 = (float4*)d_out;

    const int n_rows = in_sizes[0] / 2;      // 100000

    // 32-row chunks -> 3125 blocks, no tail (100000 = 3125 * 32).
    int chunk = 32;
    int grid  = (n_rows + chunk - 1) / chunk;

    iou_distance_kernel<<<grid, 256>>>(lhs, rhs4, out4, chunk, n_rows);
}